// round 16
// baseline (speedup 1.0000x reference)
#include <cuda_runtime.h>
#include <cuda_fp16.h>
#include <stdint.h>
#include <math.h>

#define B_    16
#define C_    64
#define H_    160
#define W_    160
#define OUT_  64
#define KEXP  4
#define HID   17
#define TEMPR 34.0f
#define HW    25600

// ---- flat padded image: [b][flat_px][64ch] fp16, 128B per pixel ----
#define PW      161
#define XGF     192
#define NPOS    25759
#define XROWS   26496
#define XREGB   3391488ULL               // 26496*128
// ---- tiling ----
#define MTILE   128
#define NT_PER_B 202                     // ceil(25759/128)
#define STRIP   452                      // 128 + 2*162
// ---- smem (swizzled, 128B rows) ----
#define OFF_X   0                        // 452*128 = 57856
#define OFF_W   57856
#define WBUF_SZ 8192
#define DYN_SMEM 74240                   // 57856 + 2*8192  (3 CTAs/SM)

__device__ __align__(128) unsigned char g_x[16*XREGB];
__device__ __align__(128) unsigned char g_wp[16*9*8192];
__device__ float g_pooled[B_*C_];
__device__ float g_aggb[B_*OUT_];

__device__ __forceinline__ uint32_t smem_u32(const void* p) {
    uint32_t a;
    asm("{ .reg .u64 t; cvta.to.shared.u64 t, %1; cvt.u32.u64 %0, t; }" : "=r"(a) : "l"(p));
    return a;
}
__device__ __forceinline__ void cp16(uint32_t dst, const void* src) {
    asm volatile("cp.async.cg.shared.global [%0], [%1], 16;" :: "r"(dst), "l"(src) : "memory");
}
#define CP_COMMIT() asm volatile("cp.async.commit_group;" ::: "memory")
#define CP_WAIT0()  asm volatile("cp.async.wait_group 0;" ::: "memory")

#define LDM4(r, a) \
    asm volatile("ldmatrix.sync.aligned.m8n8.x4.shared.b16 {%0,%1,%2,%3}, [%4];" \
        : "=r"((r)[0]), "=r"((r)[1]), "=r"((r)[2]), "=r"((r)[3]) : "r"(a))
#define MMA16816(d, a, b) \
    asm volatile("mma.sync.aligned.m16n8k16.row.col.f32.f16.f16.f32 " \
        "{%0,%1,%2,%3}, {%4,%5,%6,%7}, {%8,%9}, {%0,%1,%2,%3};" \
        : "+f"((d)[0]), "+f"((d)[1]), "+f"((d)[2]), "+f"((d)[3]) \
        : "r"((a)[0]), "r"((a)[1]), "r"((a)[2]), "r"((a)[3]), "r"((b)[0]), "r"((b)[1]))

// swizzled smem offset for (row, 16B-col c): row*128 + ((c ^ (row&7))<<4)
__device__ __forceinline__ uint32_t swz(uint32_t row, uint32_t c) {
    return row*128u + ((c ^ (row & 7u)) << 4);
}

// ================= preprocessing =================
// transpose x -> g_x (fp16) + fused global-average-pool partial sums
__global__ __launch_bounds__(256)
void xprep_kernel(const float* __restrict__ x) {
    __shared__ float s[64*33];
    int h  = blockIdx.x;
    int w0 = blockIdx.y * 32;
    int b  = blockIdx.z;
    int t  = threadIdx.x;
    int wd = t >> 5, lane = t & 31;
    #pragma unroll
    for (int i = 0; i < 8; i++) {
        int c = i*8 + wd;
        s[c*33 + lane] = x[(((size_t)b*C_ + c)*H_ + h)*W_ + w0 + lane];
    }
    __syncthreads();
    int px = t >> 3, g = t & 7;
    unsigned short hs[8];
    #pragma unroll
    for (int j = 0; j < 8; j++) {
        float v = s[(8*g + j)*33 + px];
        hs[j] = __half_as_ushort(__float2half_rn(v));
    }
    uint4 hv;
    hv.x = hs[0] | ((uint32_t)hs[1] << 16); hv.y = hs[2] | ((uint32_t)hs[3] << 16);
    hv.z = hs[4] | ((uint32_t)hs[5] << 16); hv.w = hs[6] | ((uint32_t)hs[7] << 16);
    uint32_t row = XGF + (uint32_t)h*PW + (uint32_t)(w0 + px);
    *(uint4*)(g_x + (size_t)b*XREGB + (size_t)row*128u + (uint32_t)g*16u) = hv;

    if (t < 64) {
        float sum = 0.f;
        #pragma unroll
        for (int p = 0; p < 32; p++) sum += s[t*33 + p];
        atomicAdd(&g_pooled[b*C_ + t], sum);
    }
}

// fused attention + weight aggregation -> fp16. grid (B, 9 taps, 4 oc-groups), 128 thr.
__global__ __launch_bounds__(128)
void wprep_kernel(const float* __restrict__ fc1,
                  const float* __restrict__ fc2,
                  const float* __restrict__ bias_p,
                  const float* __restrict__ weight) {
    int b = blockIdx.x, tap = blockIdx.y, zg = blockIdx.z;
    int t = threadIdx.x, lane = t & 31;
    __shared__ float attn_s[KEXP];

    if (t < 32) {
        float hid = 0.f;
        if (lane < HID) {
            #pragma unroll
            for (int c = 0; c < C_; c++)
                hid += g_pooled[b*C_ + c] * (1.0f/(float)HW) * fc1[lane*C_ + c];
            hid = fmaxf(hid, 0.f);
        }
        float lg = 0.f;
        #pragma unroll
        for (int j = 0; j < HID; j++) {
            float hj = __shfl_sync(0xffffffffu, hid, j);
            if (lane < KEXP) lg += hj * fc2[lane*HID + j];
        }
        lg *= (1.0f/TEMPR);
        float l0 = __shfl_sync(0xffffffffu, lg, 0);
        float l1 = __shfl_sync(0xffffffffu, lg, 1);
        float l2 = __shfl_sync(0xffffffffu, lg, 2);
        float l3 = __shfl_sync(0xffffffffu, lg, 3);
        if (lane == 0) {
            float m = fmaxf(fmaxf(l0,l1), fmaxf(l2,l3));
            float e0 = expf(l0-m), e1 = expf(l1-m), e2 = expf(l2-m), e3 = expf(l3-m);
            float inv = 1.f/(e0+e1+e2+e3);
            attn_s[0] = e0*inv; attn_s[1] = e1*inv; attn_s[2] = e2*inv; attn_s[3] = e3*inv;
        }
    }
    __syncthreads();
    float a0 = attn_s[0], a1 = attn_s[1], a2 = attn_s[2], a3 = attn_s[3];

    if (tap == 0 && zg == 0 && t < OUT_) {
        g_aggb[b*OUT_ + t] = a0*bias_p[t] + a1*bias_p[OUT_ + t]
                           + a2*bias_p[2*OUT_ + t] + a3*bias_p[3*OUT_ + t];
    }

    int oc = zg*16 + (t >> 3);
    int g  = t & 7;
    unsigned short hs[8];
    #pragma unroll
    for (int j = 0; j < 8; j++) {
        int c = 8*g + j;
        size_t e = ((size_t)oc*C_ + c)*9 + tap;
        size_t stride = (size_t)OUT_*C_*9;
        float s = a0*weight[e] + a1*weight[e + stride]
                + a2*weight[e + 2*stride] + a3*weight[e + 3*stride];
        hs[j] = __half_as_ushort(__float2half_rn(s));
    }
    uint4 hv;
    hv.x = hs[0] | ((uint32_t)hs[1] << 16); hv.y = hs[2] | ((uint32_t)hs[3] << 16);
    hv.z = hs[4] | ((uint32_t)hs[5] << 16); hv.w = hs[6] | ((uint32_t)hs[7] << 16);
    size_t tb = ((size_t)b*9 + tap)*8192;
    *(uint4*)(g_wp + tb + (size_t)oc*128u + g*16u) = hv;
}

// ================= conv: fp16 implicit GEMM, 3 CTAs/SM, swizzled smem =================
// CTA: 128 px x 64 oc, 8 warps (4m x 2n), warp tile 32 px x 32 oc.
__global__ __launch_bounds__(256, 3)
void conv_mma_kernel(float* __restrict__ out) {
    extern __shared__ unsigned char smem[];
    uint32_t sb = smem_u32(smem);
    int tid = threadIdx.x, wid = tid >> 5, lane = tid & 31;
    int b = blockIdx.y;
    int n0 = blockIdx.x * MTILE;

    // reset pooled accumulators for next replay (all wprep reads are done)
    if (blockIdx.x == 0 && tid < C_) g_pooled[b*C_ + tid] = 0.f;

    // ---- stage x strip (swizzled) + W tap0 ----
    {
        const unsigned char* xs = g_x + (size_t)b*XREGB + (size_t)(XGF + n0 - 162)*128;
        for (int i = tid; i < STRIP*8; i += 256) {
            uint32_t r = (uint32_t)i >> 3, c = (uint32_t)i & 7;
            cp16(sb + OFF_X + swz(r, c), xs + (size_t)r*128 + c*16);
        }
        const unsigned char* ws = g_wp + (size_t)b*9*8192;
        for (int i = tid; i < 64*8; i += 256) {
            uint32_t r = (uint32_t)i >> 3, c = (uint32_t)i & 7;
            cp16(sb + OFF_W + swz(r, c), ws + (size_t)r*128 + c*16);
        }
        CP_COMMIT();
        CP_WAIT0();
        __syncthreads();
    }

    const int wm = (wid & 3) * 32;          // 32 px per warp (2 m16 tiles)
    const int wn = (wid >> 2) * 32;         // 32 oc per warp (4 n8 tiles)
    const int shifts[9] = {-162,-161,-160,-1,0,1,160,161,162};

    float acc[2][4][4];
    #pragma unroll
    for (int i = 0; i < 2; i++)
        #pragma unroll
        for (int j = 0; j < 4; j++)
            #pragma unroll
            for (int k = 0; k < 4; k++) acc[i][j][k] = 0.f;

    // per-lane row/col decomposition for ldmatrix
    const uint32_t a_row0 = 162u + (uint32_t)wm + (uint32_t)(lane & 15);
    const uint32_t a_c0   = (uint32_t)(lane >> 4);            // | (ks<<1)
    const uint32_t b_row0 = (uint32_t)(wn + (lane & 7) + ((lane >> 4) & 1)*8);
    const uint32_t b_c0   = (uint32_t)((lane >> 3) & 1);      // | (ks<<1)

    #pragma unroll
    for (int tap = 0; tap < 9; tap++) {
        if (tap < 8) {
            const unsigned char* ws = g_wp + ((size_t)b*9 + tap + 1)*8192;
            uint32_t wdst = sb + OFF_W + ((tap + 1) & 1)*WBUF_SZ;
            for (int i = tid; i < 64*8; i += 256) {
                uint32_t r = (uint32_t)i >> 3, c = (uint32_t)i & 7;
                cp16(wdst + swz(r, c), ws + (size_t)r*128 + c*16);
            }
            CP_COMMIT();
        }

        uint32_t wb = sb + OFF_W + (uint32_t)(tap & 1)*WBUF_SZ;
        uint32_t arow_t = a_row0 + (uint32_t)shifts[tap];

        #pragma unroll
        for (int ks = 0; ks < 4; ks++) {
            uint32_t ca = a_c0 | ((uint32_t)ks << 1);
            uint32_t cb = b_c0 | ((uint32_t)ks << 1);
            uint32_t bf[2][4];
            #pragma unroll
            for (int nh = 0; nh < 2; nh++) {
                uint32_t row = b_row0 + (uint32_t)nh*16;
                LDM4(bf[nh], wb + swz(row, cb));
            }
            #pragma unroll
            for (int mi = 0; mi < 2; mi++) {
                uint32_t row = arow_t + (uint32_t)mi*16;
                uint32_t af[4];
                LDM4(af, sb + OFF_X + swz(row, ca));
                #pragma unroll
                for (int nh = 0; nh < 2; nh++) {
                    MMA16816(acc[mi][nh*2 + 0], af, (bf[nh] + 0));
                    MMA16816(acc[mi][nh*2 + 1], af, (bf[nh] + 2));
                }
            }
        }
        if (tap < 8) { CP_WAIT0(); }
        __syncthreads();
    }

    // ---- epilogue: direct stores with flat->(h,w) filtering ----
    int g = lane >> 2, tc = lane & 3;
    #pragma unroll
    for (int mi = 0; mi < 2; mi++) {
        #pragma unroll
        for (int ni = 0; ni < 4; ni++) {
            int oc = wn + ni*8 + tc*2;
            float2 bias = *(const float2*)&g_aggb[b*OUT_ + oc];
            int pxA = n0 + wm + mi*16 + g;
            #pragma unroll
            for (int half = 0; half < 2; half++) {
                int px = pxA + half*8;
                int h = px / PW;
                int w = px - h*PW;
                if (w < W_ && h < H_) {
                    size_t o = (((size_t)b*OUT_ + oc)*H_ + h)*W_ + w;
                    out[o]      = acc[mi][ni][half*2 + 0] + bias.x;
                    out[o + HW] = acc[mi][ni][half*2 + 1] + bias.y;
                }
            }
        }
    }
}

extern "C" void kernel_launch(void* const* d_in, const int* in_sizes, int n_in,
                              void* d_out, int out_size) {
    const float* x      = (const float*)d_in[0];
    const float* fc1    = (const float*)d_in[1];
    const float* fc2    = (const float*)d_in[2];
    const float* weight = (const float*)d_in[3];
    const float* bias_p = (const float*)d_in[4];
    float* out = (float*)d_out;

    cudaFuncSetAttribute(conv_mma_kernel, cudaFuncAttributeMaxDynamicSharedMemorySize, DYN_SMEM);

    xprep_kernel<<<dim3(H_, 5, B_), 256>>>(x);
    wprep_kernel<<<dim3(B_, 9, 4), 128>>>(fc1, fc2, bias_p, weight);
    conv_mma_kernel<<<dim3(NT_PER_B, B_), 256, DYN_SMEM>>>(out);
}

// round 17
// speedup vs baseline: 1.0408x; 1.0408x over previous
#include <cuda_runtime.h>
#include <cuda_fp16.h>
#include <stdint.h>
#include <math.h>

#define B_    16
#define C_    64
#define H_    160
#define W_    160
#define OUT_  64
#define KEXP  4
#define HID   17
#define TEMPR 34.0f
#define HW    25600

// ---- flat padded image: [b][flat_px][64ch] fp16, 128B per pixel ----
#define PW      161
#define XGF     192
#define NPOS    25759
#define XROWS   26496
#define XREGB   3391488ULL               // 26496*128
// ---- tiling ----
#define MTILE   256
#define NT_PER_B 101                     // ceil(25759/256)
#define NTILES_TOT (NT_PER_B*B_)         // 1616
#define STRIP   580                      // 256 + 2*162
#define SROW_B  144
// ---- smem ----
#define OFF_X   0                        // 580*144 = 83520
#define OFF_W   83520
#define WBUF_SZ 9216
#define DYN_SMEM 101952                  // 2 CTAs/SM

__device__ __align__(128) unsigned char g_x[16*XREGB];
__device__ __align__(128) unsigned char g_wp[16*9*8192];
__device__ float g_pooled[B_*C_];
__device__ float g_aggb[B_*OUT_];
__device__ unsigned int g_tile_ctr;

__device__ __forceinline__ uint32_t smem_u32(const void* p) {
    uint32_t a;
    asm("{ .reg .u64 t; cvta.to.shared.u64 t, %1; cvt.u32.u64 %0, t; }" : "=r"(a) : "l"(p));
    return a;
}
__device__ __forceinline__ void cp16(uint32_t dst, const void* src) {
    asm volatile("cp.async.cg.shared.global [%0], [%1], 16;" :: "r"(dst), "l"(src) : "memory");
}
#define CP_COMMIT() asm volatile("cp.async.commit_group;" ::: "memory")
#define CP_WAIT0()  asm volatile("cp.async.wait_group 0;" ::: "memory")

#define LDM4(r, a) \
    asm volatile("ldmatrix.sync.aligned.m8n8.x4.shared.b16 {%0,%1,%2,%3}, [%4];" \
        : "=r"((r)[0]), "=r"((r)[1]), "=r"((r)[2]), "=r"((r)[3]) : "r"(a))
#define MMA16816(d, a, b) \
    asm volatile("mma.sync.aligned.m16n8k16.row.col.f32.f16.f16.f32 " \
        "{%0,%1,%2,%3}, {%4,%5,%6,%7}, {%8,%9}, {%0,%1,%2,%3};" \
        : "+f"((d)[0]), "+f"((d)[1]), "+f"((d)[2]), "+f"((d)[3]) \
        : "r"((a)[0]), "r"((a)[1]), "r"((a)[2]), "r"((a)[3]), "r"((b)[0]), "r"((b)[1]))

// ================= preprocessing =================
// transpose x -> g_x (fp16), 5 w-tiles per block, double-buffered; fused pooling
__global__ __launch_bounds__(256)
void xprep_kernel(const float* __restrict__ x) {
    __shared__ float s[2][64*33];
    int h = blockIdx.x, b = blockIdx.y;
    int t = threadIdx.x, wd = t >> 5, lane = t & 31;
    int px = t >> 3, g = t & 7;
    float pool = 0.f;
    #pragma unroll
    for (int it = 0; it < 5; ++it) {
        int w0 = it*32;
        float* sb_ = s[it & 1];
        #pragma unroll
        for (int i = 0; i < 8; i++) {
            int c = i*8 + wd;
            sb_[c*33 + lane] = x[(((size_t)b*C_ + c)*H_ + h)*W_ + w0 + lane];
        }
        __syncthreads();
        unsigned short hs[8];
        #pragma unroll
        for (int j = 0; j < 8; j++)
            hs[j] = __half_as_ushort(__float2half_rn(sb_[(8*g + j)*33 + px]));
        uint4 hv;
        hv.x = hs[0] | ((uint32_t)hs[1] << 16); hv.y = hs[2] | ((uint32_t)hs[3] << 16);
        hv.z = hs[4] | ((uint32_t)hs[5] << 16); hv.w = hs[6] | ((uint32_t)hs[7] << 16);
        uint32_t row = XGF + (uint32_t)h*PW + (uint32_t)(w0 + px);
        *(uint4*)(g_x + (size_t)b*XREGB + (size_t)row*128u + (uint32_t)g*16u) = hv;
        if (t < 64) {
            #pragma unroll
            for (int p = 0; p < 32; p++) pool += sb_[t*33 + p];
        }
    }
    if (t < 64) atomicAdd(&g_pooled[b*C_ + t], pool);
}

// fused attention + weight aggregation -> fp16. grid (B, 9 taps, 4 oc-groups), 128 thr.
__global__ __launch_bounds__(128)
void wprep_kernel(const float* __restrict__ fc1,
                  const float* __restrict__ fc2,
                  const float* __restrict__ bias_p,
                  const float* __restrict__ weight) {
    int b = blockIdx.x, tap = blockIdx.y, zg = blockIdx.z;
    int t = threadIdx.x, lane = t & 31;
    __shared__ float attn_s[KEXP];

    if (t < 32) {
        float hid = 0.f;
        if (lane < HID) {
            #pragma unroll
            for (int c = 0; c < C_; c++)
                hid += g_pooled[b*C_ + c] * (1.0f/(float)HW) * fc1[lane*C_ + c];
            hid = fmaxf(hid, 0.f);
        }
        float lg = 0.f;
        #pragma unroll
        for (int j = 0; j < HID; j++) {
            float hj = __shfl_sync(0xffffffffu, hid, j);
            if (lane < KEXP) lg += hj * fc2[lane*HID + j];
        }
        lg *= (1.0f/TEMPR);
        float l0 = __shfl_sync(0xffffffffu, lg, 0);
        float l1 = __shfl_sync(0xffffffffu, lg, 1);
        float l2 = __shfl_sync(0xffffffffu, lg, 2);
        float l3 = __shfl_sync(0xffffffffu, lg, 3);
        if (lane == 0) {
            float m = fmaxf(fmaxf(l0,l1), fmaxf(l2,l3));
            float e0 = expf(l0-m), e1 = expf(l1-m), e2 = expf(l2-m), e3 = expf(l3-m);
            float inv = 1.f/(e0+e1+e2+e3);
            attn_s[0] = e0*inv; attn_s[1] = e1*inv; attn_s[2] = e2*inv; attn_s[3] = e3*inv;
        }
    }
    __syncthreads();
    float a0 = attn_s[0], a1 = attn_s[1], a2 = attn_s[2], a3 = attn_s[3];

    if (tap == 0 && zg == 0) {
        if (t < OUT_)
            g_aggb[b*OUT_ + t] = a0*bias_p[t] + a1*bias_p[OUT_ + t]
                               + a2*bias_p[2*OUT_ + t] + a3*bias_p[3*OUT_ + t];
        if (b == 0 && t == 64) g_tile_ctr = 0;     // reset work-steal counter
    }

    int oc = zg*16 + (t >> 3);
    int g  = t & 7;
    unsigned short hs[8];
    #pragma unroll
    for (int j = 0; j < 8; j++) {
        int c = 8*g + j;
        size_t e = ((size_t)oc*C_ + c)*9 + tap;
        size_t stride = (size_t)OUT_*C_*9;
        float s = a0*weight[e] + a1*weight[e + stride]
                + a2*weight[e + 2*stride] + a3*weight[e + 3*stride];
        hs[j] = __half_as_ushort(__float2half_rn(s));
    }
    uint4 hv;
    hv.x = hs[0] | ((uint32_t)hs[1] << 16); hv.y = hs[2] | ((uint32_t)hs[3] << 16);
    hv.z = hs[4] | ((uint32_t)hs[5] << 16); hv.w = hs[6] | ((uint32_t)hs[7] << 16);
    size_t tb = ((size_t)b*9 + tap)*8192;
    *(uint4*)(g_wp + tb + (size_t)oc*128u + g*16u) = hv;
}

// ================= conv: persistent work-stealing fp16 implicit GEMM =================
// 296 CTAs (2/SM), each steals 256-px tiles. 8 warps (4m x 2n), warp 64px x 32oc.
__global__ __launch_bounds__(256, 2)
void conv_mma_kernel(float* __restrict__ out) {
    extern __shared__ unsigned char smem[];
    __shared__ int s_tile;
    uint32_t sb = smem_u32(smem);
    int tid = threadIdx.x, wid = tid >> 5, lane = tid & 31;

    // reset pooled accumulators for next replay (wprep reads are done)
    if (blockIdx.x == 0)
        for (int i = tid; i < B_*C_; i += 256) g_pooled[i] = 0.f;

    const int wm = (wid & 3) * 64;
    const int wn = (wid >> 2) * 32;
    const int shifts[9] = {-162,-161,-160,-1,0,1,160,161,162};
    const uint32_t a_lane = (uint32_t)(lane & 15)*SROW_B + (uint32_t)(lane >> 4)*16;
    const uint32_t b_lane = (uint32_t)((lane & 7) + ((lane >> 4) & 1)*8)*SROW_B
                          + (uint32_t)((lane >> 3) & 1)*16;

    for (;;) {
        if (tid == 0) s_tile = (int)atomicAdd(&g_tile_ctr, 1u);
        __syncthreads();                       // broadcast + protects smem reuse
        int tile = s_tile;
        if (tile >= NTILES_TOT) break;
        int b  = tile / NT_PER_B;
        int n0 = (tile - b*NT_PER_B) * MTILE;

        // ---- stage x strip + W tap0 ----
        const unsigned char* xs = g_x + (size_t)b*XREGB + (size_t)(XGF + n0 - 162)*128;
        for (int i = tid; i < STRIP*8; i += 256) {
            int r = i >> 3, c = i & 7;
            cp16(sb + OFF_X + r*SROW_B + c*16, xs + (size_t)r*128 + c*16);
        }
        const unsigned char* ws0 = g_wp + (size_t)b*9*8192;
        for (int i = tid; i < 64*8; i += 256) {
            int r = i >> 3, c = i & 7;
            cp16(sb + OFF_W + r*SROW_B + c*16, ws0 + (size_t)r*128 + c*16);
        }
        CP_COMMIT();
        CP_WAIT0();
        __syncthreads();

        float acc[4][4][4];
        #pragma unroll
        for (int i = 0; i < 4; i++)
            #pragma unroll
            for (int j = 0; j < 4; j++)
                #pragma unroll
                for (int k = 0; k < 4; k++) acc[i][j][k] = 0.f;

        #pragma unroll
        for (int tap = 0; tap < 9; tap++) {
            if (tap < 8) {
                const unsigned char* ws = g_wp + ((size_t)b*9 + tap + 1)*8192;
                uint32_t wdst = sb + OFF_W + ((tap + 1) & 1)*WBUF_SZ;
                for (int i = tid; i < 64*8; i += 256) {
                    int r = i >> 3, c = i & 7;
                    cp16(wdst + r*SROW_B + c*16, ws + (size_t)r*128 + c*16);
                }
                CP_COMMIT();
            }

            uint32_t wbuf = sb + OFF_W + (tap & 1)*WBUF_SZ;
            uint32_t xrow = sb + OFF_X + (uint32_t)(162 + shifts[tap] + wm)*SROW_B + a_lane;

            #pragma unroll
            for (int ks = 0; ks < 4; ks++) {
                uint32_t kb = (uint32_t)ks*32;
                uint32_t bf[2][4];
                #pragma unroll
                for (int nh = 0; nh < 2; nh++) {
                    uint32_t ba = wbuf + (uint32_t)(wn + nh*16)*SROW_B + b_lane + kb;
                    LDM4(bf[nh], ba);
                }
                #pragma unroll
                for (int mi = 0; mi < 4; mi++) {
                    uint32_t af[4];
                    LDM4(af, xrow + (uint32_t)mi*(16*SROW_B) + kb);
                    #pragma unroll
                    for (int nh = 0; nh < 2; nh++) {
                        MMA16816(acc[mi][nh*2 + 0], af, (bf[nh] + 0));
                        MMA16816(acc[mi][nh*2 + 1], af, (bf[nh] + 2));
                    }
                }
            }
            if (tap < 8) { CP_WAIT0(); }
            __syncthreads();
        }

        // ---- epilogue ----
        int g = lane >> 2, tc = lane & 3;
        #pragma unroll
        for (int mi = 0; mi < 4; mi++) {
            #pragma unroll
            for (int ni = 0; ni < 4; ni++) {
                int oc = wn + ni*8 + tc*2;
                float2 bias = *(const float2*)&g_aggb[b*OUT_ + oc];
                int pxA = n0 + wm + mi*16 + g;
                #pragma unroll
                for (int half = 0; half < 2; half++) {
                    int px = pxA + half*8;
                    int h = px / PW;
                    int w = px - h*PW;
                    if (w < W_ && h < H_) {
                        size_t o = (((size_t)b*OUT_ + oc)*H_ + h)*W_ + w;
                        out[o]      = acc[mi][ni][half*2 + 0] + bias.x;
                        out[o + HW] = acc[mi][ni][half*2 + 1] + bias.y;
                    }
                }
            }
        }
    }
}

extern "C" void kernel_launch(void* const* d_in, const int* in_sizes, int n_in,
                              void* d_out, int out_size) {
    const float* x      = (const float*)d_in[0];
    const float* fc1    = (const float*)d_in[1];
    const float* fc2    = (const float*)d_in[2];
    const float* weight = (const float*)d_in[3];
    const float* bias_p = (const float*)d_in[4];
    float* out = (float*)d_out;

    cudaFuncSetAttribute(conv_mma_kernel, cudaFuncAttributeMaxDynamicSharedMemorySize, DYN_SMEM);

    xprep_kernel<<<dim3(H_, B_), 256>>>(x);
    wprep_kernel<<<dim3(B_, 9, 4), 128>>>(fc1, fc2, bias_p, weight);
    conv_mma_kernel<<<296, 256, DYN_SMEM>>>(out);
}